// round 6
// baseline (speedup 1.0000x reference)
#include <cuda_runtime.h>

#define KDIM  32
#define TABN  1024
#define COEF  0.3989422804014327f
#define EPS   2.220446049250313e-16f

// Interpolation grid for the 64 univariate functions
#define G     160
#define GPAD  36                    // row stride in floats (float4-aligned, bank-rotating)
#define XMIN  (-6.5f)
#define XMAX  (6.5f)
#define DX    ((XMAX - XMIN) / (G - 1))
#define DXI   ((G - 1) / (XMAX - XMIN))

// lik(x0,x1) = sum_a h_a(x0) * g_a(x1)   (rank-32 separable form)
__device__ float d_gt[G * GPAD];
__device__ float d_ht[G * GPAD];

__device__ __forceinline__ float ex2(float x) {
    float r;
    asm("ex2.approx.ftz.f32 %0, %1;" : "=f"(r) : "f"(x));
    return r;
}

// ---------------- Fused precompute: weights + tables (unchanged, ~2-4us) ----
#define TB_BLOCKS  20
#define TB_THREADS 512

__global__ __launch_bounds__(TB_THREADS)
void tables_fused_kernel(const float* __restrict__ Wk0,
                         const float* __restrict__ W10,
                         const float* __restrict__ W21,
                         const float* __restrict__ mu,
                         const float* __restrict__ sigma) {
    __shared__ float sw10[TABN], sw21[TABN];
    __shared__ float s10[KDIM], s21[KDIM], w0n[KDIM];
    __shared__ float wcg[TABN], wch[TABN], smu[TABN], sinv[TABN];
    int tid = threadIdx.x;

    for (int i = tid; i < TABN; i += TB_THREADS) {
        sw10[i] = expf(W10[i]);
        sw21[i] = expf(W21[i]);
    }
    __syncthreads();

    if (tid < KDIM) {
        float a10 = 0.f, a21 = 0.f;
        for (int i = 0; i < KDIM; i++) {
            a10 += sw10[i * KDIM + tid];
            a21 += sw21[i * KDIM + tid];
        }
        s10[tid] = a10;
        s21[tid] = a21;
        float es = 0.f;
        for (int i = 0; i < KDIM; i++) es += expf(Wk0[i]);
        w0n[tid] = expf(Wk0[tid]) / es;
    }
    __syncthreads();

    for (int i = tid; i < TABN; i += TB_THREADS) {
        int b = i & 31;
        float s = sigma[i];
        float inv = 1.0f / s;
        smu[i]  = mu[i];
        sinv[i] = inv;
        wcg[i] = (sw21[i] / s21[b]) * COEF * inv;
        wch[i] = (sw10[i] / s10[b]) * w0n[b] * COEF * inv;
    }
    __syncthreads();

    int idx = blockIdx.x * TB_THREADS + tid;
    int tbl = idx / (G * KDIM);
    int rem = idx - tbl * (G * KDIM);
    int t = rem >> 5;
    int a = rem & 31;

    float x = XMIN + (float)t * DX;
    const float K2 = -0.72134752044448170f;       // -0.5 * log2(e)
    float acc = 0.f;
    if (tbl == 0) {
#pragma unroll
        for (int m = 0; m < KDIM; m++) {
            int e = m * KDIM + a;
            float z = (x - smu[e]) * sinv[e];
            acc += wcg[e] * ex2(K2 * z * z);
        }
        d_gt[t * GPAD + a] = acc;
    } else {
#pragma unroll
        for (int m = 0; m < KDIM; m++) {
            int b = (m + a) & 31;
            int e = a * KDIM + b;
            float z = (x - smu[e]) * sinv[e];
            acc += wch[e] * ex2(K2 * z * z);
        }
        d_ht[t * GPAD + a] = acc;
    }
}

// ---------------- Per-sample cubic interpolation ----------------
struct Look {
    const float *r0, *r1, *r2, *r3;
    float a, b, c, d;
};

__device__ __forceinline__ Look mk_look(const float* tab, float x) {
    Look L;
    float u = (x - XMIN) * DXI;
    u = fminf(fmaxf(u, 1.0f), (float)(G - 2) - 1e-3f);
    int j = (int)u;
    float t = u - (float)j;
    float tm1 = t - 1.f, tm2 = t - 2.f, tp1 = t + 1.f;
    L.a = -t * tm1 * tm2 * (1.f / 6.f);
    L.b = tp1 * tm1 * tm2 * 0.5f;
    L.c = -tp1 * t * tm2 * 0.5f;
    L.d = tp1 * t * tm1 * (1.f / 6.f);
    L.r0 = tab + (j - 1) * GPAD;
    L.r1 = L.r0 + GPAD;
    L.r2 = L.r1 + GPAD;
    L.r3 = L.r2 + GPAD;
    return L;
}

__device__ __forceinline__ float lerp4(const Look& L, int off, float4& o0,
                                       float4& o1, float4& o2, float4& o3) {
    o0 = *(const float4*)(L.r0 + off);
    o1 = *(const float4*)(L.r1 + off);
    o2 = *(const float4*)(L.r2 + off);
    o3 = *(const float4*)(L.r3 + off);
    return 0.f;
}

__device__ __forceinline__ float comb(const Look& L, float v0, float v1,
                                      float v2, float v3) {
    return fmaf(L.a, v0, fmaf(L.b, v1, fmaf(L.c, v2, L.d * v3)));
}

__device__ __forceinline__ float eval_one(const float* sg, const float* sh, float2 p) {
    Look Lg = mk_look(sg, p.y);
    float gval[KDIM];
#pragma unroll
    for (int c = 0; c < 8; c++) {
        float4 a0, a1, a2, a3;
        lerp4(Lg, 4 * c, a0, a1, a2, a3);
        gval[4*c+0] = comb(Lg, a0.x, a1.x, a2.x, a3.x);
        gval[4*c+1] = comb(Lg, a0.y, a1.y, a2.y, a3.y);
        gval[4*c+2] = comb(Lg, a0.z, a1.z, a2.z, a3.z);
        gval[4*c+3] = comb(Lg, a0.w, a1.w, a2.w, a3.w);
    }
    Look Lh = mk_look(sh, p.x);
    float l0 = 0.f, l1 = 0.f;
#pragma unroll
    for (int c = 0; c < 8; c++) {
        float4 b0, b1, b2, b3;
        lerp4(Lh, 4 * c, b0, b1, b2, b3);
        l0 = fmaf(comb(Lh, b0.x, b1.x, b2.x, b3.x), gval[4*c+0], l0);
        l1 = fmaf(comb(Lh, b0.y, b1.y, b2.y, b3.y), gval[4*c+1], l1);
        l0 = fmaf(comb(Lh, b0.z, b1.z, b2.z, b3.z), gval[4*c+2], l0);
        l1 = fmaf(comb(Lh, b0.w, b1.w, b2.w, b3.w), gval[4*c+3], l1);
    }
    return fmaxf(l0 + l1, 0.f);
}

// Two samples per thread, interleaved at chunk level: each inner iteration
// issues 8 independent LDS.128 before the FMA trees (2x MLP vs one chain).
__device__ __forceinline__ void eval_pair(const float* sg, const float* sh,
                                          float2 pA, float2 pB,
                                          float& likA, float& likB) {
    Look LgA = mk_look(sg, pA.y);
    Look LgB = mk_look(sg, pB.y);
    float gvA[KDIM], gvB[KDIM];
#pragma unroll
    for (int c = 0; c < 8; c++) {
        float4 a0, a1, a2, a3, b0, b1, b2, b3;
        lerp4(LgA, 4 * c, a0, a1, a2, a3);
        lerp4(LgB, 4 * c, b0, b1, b2, b3);
        gvA[4*c+0] = comb(LgA, a0.x, a1.x, a2.x, a3.x);
        gvB[4*c+0] = comb(LgB, b0.x, b1.x, b2.x, b3.x);
        gvA[4*c+1] = comb(LgA, a0.y, a1.y, a2.y, a3.y);
        gvB[4*c+1] = comb(LgB, b0.y, b1.y, b2.y, b3.y);
        gvA[4*c+2] = comb(LgA, a0.z, a1.z, a2.z, a3.z);
        gvB[4*c+2] = comb(LgB, b0.z, b1.z, b2.z, b3.z);
        gvA[4*c+3] = comb(LgA, a0.w, a1.w, a2.w, a3.w);
        gvB[4*c+3] = comb(LgB, b0.w, b1.w, b2.w, b3.w);
    }
    Look LhA = mk_look(sh, pA.x);
    Look LhB = mk_look(sh, pB.x);
    float lA0 = 0.f, lA1 = 0.f, lB0 = 0.f, lB1 = 0.f;
#pragma unroll
    for (int c = 0; c < 8; c++) {
        float4 a0, a1, a2, a3, b0, b1, b2, b3;
        lerp4(LhA, 4 * c, a0, a1, a2, a3);
        lerp4(LhB, 4 * c, b0, b1, b2, b3);
        lA0 = fmaf(comb(LhA, a0.x, a1.x, a2.x, a3.x), gvA[4*c+0], lA0);
        lB0 = fmaf(comb(LhB, b0.x, b1.x, b2.x, b3.x), gvB[4*c+0], lB0);
        lA1 = fmaf(comb(LhA, a0.y, a1.y, a2.y, a3.y), gvA[4*c+1], lA1);
        lB1 = fmaf(comb(LhB, b0.y, b1.y, b2.y, b3.y), gvB[4*c+1], lB1);
        lA0 = fmaf(comb(LhA, a0.z, a1.z, a2.z, a3.z), gvA[4*c+2], lA0);
        lB0 = fmaf(comb(LhB, b0.z, b1.z, b2.z, b3.z), gvB[4*c+2], lB0);
        lA1 = fmaf(comb(LhA, a0.w, a1.w, a2.w, a3.w), gvA[4*c+3], lA1);
        lB1 = fmaf(comb(LhB, b0.w, b1.w, b2.w, b3.w), gvB[4*c+3], lB1);
    }
    likA = fmaxf(lA0 + lA1, 0.f);
    likB = fmaxf(lB0 + lB1, 0.f);
}

#define IB 192

__global__ __launch_bounds__(256)
void interp_kernel(const float2* __restrict__ X, float* __restrict__ out, int N) {
    __shared__ float sg[G * GPAD];
    __shared__ float sh[G * GPAD];
    {
        float4* dg = (float4*)sg;
        float4* dh = (float4*)sh;
        const float4* sgt = (const float4*)d_gt;
        const float4* sht = (const float4*)d_ht;
        const int n4 = G * GPAD / 4;
        for (int i = threadIdx.x; i < n4; i += 256) {
            dg[i] = sgt[i];
            dh[i] = sht[i];
        }
    }
    __syncthreads();

    const int T = IB * 256;
    int t0 = blockIdx.x * 256 + threadIdx.x;

    int n0 = t0, n1 = t0 + T;
    if (n1 < N) {
        float likA, likB;
        eval_pair(sg, sh, X[n0], X[n1], likA, likB);
        out[n0] = logf(likA + EPS);
        out[n1] = logf(likB + EPS);
    } else if (n0 < N) {
        out[n0] = logf(eval_one(sg, sh, X[n0]) + EPS);
    }
    for (int n = t0 + 2 * T; n < N; n += T)
        out[n] = logf(eval_one(sg, sh, X[n]) + EPS);
}

extern "C" void kernel_launch(void* const* d_in, const int* in_sizes, int n_in,
                              void* d_out, int out_size) {
    const float* X     = (const float*)d_in[0];
    const float* Wk0   = (const float*)d_in[1];
    const float* W10   = (const float*)d_in[2];
    const float* W21   = (const float*)d_in[3];
    const float* mu    = (const float*)d_in[4];
    const float* sigma = (const float*)d_in[5];
    int N = in_sizes[0] / 2;

    tables_fused_kernel<<<TB_BLOCKS, TB_THREADS>>>(Wk0, W10, W21, mu, sigma);
    interp_kernel<<<IB, 256>>>((const float2*)X, (float*)d_out, N);
}

// round 7
// speedup vs baseline: 1.1488x; 1.1488x over previous
#include <cuda_runtime.h>

#define KDIM  32
#define TABN  1024
#define COEF  0.3989422804014327f
#define EPS   2.220446049250313e-16f

// Interpolation grid for the 64 univariate functions
#define G     160
#define GPAD  36                    // row stride in floats (float4-aligned, bank-rotating)
#define XMIN  (-6.5f)
#define XMAX  (6.5f)
#define DX    ((XMAX - XMIN) / (G - 1))
#define DXI   ((G - 1) / (XMAX - XMIN))

// lik(x0,x1) = sum_a h_a(x0) * g_a(x1)   (rank-32 separable form)
__device__ float d_gt[G * GPAD];
__device__ float d_ht[G * GPAD];

__device__ __forceinline__ float ex2(float x) {
    float r;
    asm("ex2.approx.ftz.f32 %0, %1;" : "=f"(r) : "f"(x));
    return r;
}

// ---------------- Fused precompute: weights + tables ----------------
#define TB_BLOCKS  40
#define TB_THREADS 256

__global__ __launch_bounds__(TB_THREADS)
void tables_fused_kernel(const float* __restrict__ Wk0,
                         const float* __restrict__ W10,
                         const float* __restrict__ W21,
                         const float* __restrict__ mu,
                         const float* __restrict__ sigma) {
    __shared__ float sw10[TABN], sw21[TABN];
    __shared__ float s10[KDIM], s21[KDIM], w0n[KDIM];
    __shared__ float wcg[TABN], wch[TABN], smu[TABN], sinv[TABN];
    int tid = threadIdx.x;

    for (int i = tid; i < TABN; i += TB_THREADS) {
        sw10[i] = expf(W10[i]);
        sw21[i] = expf(W21[i]);
    }
    __syncthreads();

    if (tid < KDIM) {
        float a10 = 0.f, a21 = 0.f;
        for (int i = 0; i < KDIM; i++) {
            a10 += sw10[i * KDIM + tid];
            a21 += sw21[i * KDIM + tid];
        }
        s10[tid] = a10;
        s21[tid] = a21;
        float es = 0.f;
        for (int i = 0; i < KDIM; i++) es += expf(Wk0[i]);
        w0n[tid] = expf(Wk0[tid]) / es;
    }
    __syncthreads();

    for (int i = tid; i < TABN; i += TB_THREADS) {
        int b = i & 31;
        float s = sigma[i];
        float inv = 1.0f / s;
        smu[i]  = mu[i];
        sinv[i] = inv;
        wcg[i] = (sw21[i] / s21[b]) * COEF * inv;
        wch[i] = (sw10[i] / s10[b]) * w0n[b] * COEF * inv;
    }
    __syncthreads();

    int idx = blockIdx.x * TB_THREADS + tid;      // [0, 2*G*KDIM)
    int tbl = idx / (G * KDIM);
    int rem = idx - tbl * (G * KDIM);
    int t = rem >> 5;
    int a = rem & 31;

    float x = XMIN + (float)t * DX;
    const float K2 = -0.72134752044448170f;       // -0.5 * log2(e)
    float acc = 0.f;
    if (tbl == 0) {
#pragma unroll
        for (int m = 0; m < KDIM; m++) {
            int e = m * KDIM + a;
            float z = (x - smu[e]) * sinv[e];
            acc += wcg[e] * ex2(K2 * z * z);
        }
        d_gt[t * GPAD + a] = acc;
    } else {
#pragma unroll
        for (int m = 0; m < KDIM; m++) {
            int b = (m + a) & 31;
            int e = a * KDIM + b;
            float z = (x - smu[e]) * sinv[e];
            acc += wch[e] * ex2(K2 * z * z);
        }
        d_ht[t * GPAD + a] = acc;
    }
}

// ---------------- Per-sample cubic interpolation, 2 threads/sample ----------
struct Look {
    const float *r0, *r1, *r2, *r3;
    float a, b, c, d;
};

__device__ __forceinline__ Look mk_look(const float* tab, float x) {
    Look L;
    float u = (x - XMIN) * DXI;
    u = fminf(fmaxf(u, 1.0f), (float)(G - 2) - 1e-3f);
    int j = (int)u;
    float t = u - (float)j;
    float tm1 = t - 1.f, tm2 = t - 2.f, tp1 = t + 1.f;
    L.a = -t * tm1 * tm2 * (1.f / 6.f);
    L.b = tp1 * tm1 * tm2 * 0.5f;
    L.c = -tp1 * t * tm2 * 0.5f;
    L.d = tp1 * t * tm1 * (1.f / 6.f);
    L.r0 = tab + (j - 1) * GPAD;
    L.r1 = L.r0 + GPAD;
    L.r2 = L.r1 + GPAD;
    L.r3 = L.r2 + GPAD;
    return L;
}

__device__ __forceinline__ float comb(const Look& L, float v0, float v1,
                                      float v2, float v3) {
    return fmaf(L.a, v0, fmaf(L.b, v1, fmaf(L.c, v2, L.d * v3)));
}

// Each thread covers 16 of the 32 channels (4 float4 chunks), its partner
// (lane^1) covers the other 16. Halves the per-thread dependent chain while
// keeping 200k threads in flight (smem-capped occ ~50%).
__global__ __launch_bounds__(256)
void interp_kernel(const float2* __restrict__ X, float* __restrict__ out, int N) {
    __shared__ float sg[G * GPAD];
    __shared__ float sh[G * GPAD];
    {
        float4* dg = (float4*)sg;
        float4* dh = (float4*)sh;
        const float4* sgt = (const float4*)d_gt;
        const float4* sht = (const float4*)d_ht;
        const int n4 = G * GPAD / 4;   // 1440
        for (int i = threadIdx.x; i < n4; i += 256) {
            dg[i] = sgt[i];
            dh[i] = sht[i];
        }
    }
    __syncthreads();

    int t0 = blockIdx.x * 256 + threadIdx.x;
    int n = t0 >> 1;
    int half = t0 & 1;
    if (n >= N) return;          // pairs exit together; shfl partner always alive

    float2 p = X[n];
    int cbase = 4 * half * 4;    // float offset of this thread's first chunk (0 or 16)

    // Phase 1: g-values for my 16 channels
    Look Lg = mk_look(sg, p.y);
    float gval[16];
#pragma unroll
    for (int c = 0; c < 4; c++) {
        int off = cbase + 4 * c;
        float4 a0 = *(const float4*)(Lg.r0 + off);
        float4 a1 = *(const float4*)(Lg.r1 + off);
        float4 a2 = *(const float4*)(Lg.r2 + off);
        float4 a3 = *(const float4*)(Lg.r3 + off);
        gval[4*c+0] = comb(Lg, a0.x, a1.x, a2.x, a3.x);
        gval[4*c+1] = comb(Lg, a0.y, a1.y, a2.y, a3.y);
        gval[4*c+2] = comb(Lg, a0.z, a1.z, a2.z, a3.z);
        gval[4*c+3] = comb(Lg, a0.w, a1.w, a2.w, a3.w);
    }

    // Phase 2: h-values for my 16 channels, fused dot with gval
    Look Lh = mk_look(sh, p.x);
    float l0 = 0.f, l1 = 0.f;
#pragma unroll
    for (int c = 0; c < 4; c++) {
        int off = cbase + 4 * c;
        float4 b0 = *(const float4*)(Lh.r0 + off);
        float4 b1 = *(const float4*)(Lh.r1 + off);
        float4 b2 = *(const float4*)(Lh.r2 + off);
        float4 b3 = *(const float4*)(Lh.r3 + off);
        l0 = fmaf(comb(Lh, b0.x, b1.x, b2.x, b3.x), gval[4*c+0], l0);
        l1 = fmaf(comb(Lh, b0.y, b1.y, b2.y, b3.y), gval[4*c+1], l1);
        l0 = fmaf(comb(Lh, b0.z, b1.z, b2.z, b3.z), gval[4*c+2], l0);
        l1 = fmaf(comb(Lh, b0.w, b1.w, b2.w, b3.w), gval[4*c+3], l1);
    }

    float lik = l0 + l1;
    lik += __shfl_xor_sync(0xFFFFFFFFu, lik, 1);   // combine the two halves

    if (half == 0)
        out[n] = logf(fmaxf(lik, 0.f) + EPS);
}

extern "C" void kernel_launch(void* const* d_in, const int* in_sizes, int n_in,
                              void* d_out, int out_size) {
    const float* X     = (const float*)d_in[0];
    const float* Wk0   = (const float*)d_in[1];
    const float* W10   = (const float*)d_in[2];
    const float* W21   = (const float*)d_in[3];
    const float* mu    = (const float*)d_in[4];
    const float* sigma = (const float*)d_in[5];
    int N = in_sizes[0] / 2;

    tables_fused_kernel<<<TB_BLOCKS, TB_THREADS>>>(Wk0, W10, W21, mu, sigma);

    int total = 2 * N;
    int nb = (total + 255) / 256;
    interp_kernel<<<nb, 256>>>((const float2*)X, (float*)d_out, N);
}